// round 1
// baseline (speedup 1.0000x reference)
#include <cuda_runtime.h>
#include <math.h>

#define N_NODES  50000
#define N_EDGES  400000
#define NCH      16
#define RCUT     10.0f
// total (e,k) work items
#define TOTAL    (N_EDGES * NCH)
// output section offsets (floats)
#define OUT1_OFF (N_NODES * NCH)         // 800000
#define OUT2_OFF (N_NODES * NCH * 4)     // 3200000

// scratch: per-edge geometry (no cudaMalloc allowed -> __device__ globals)
__device__ float4 g_unit[N_EDGES];   // (ux, uy, uz, unused)
__device__ float  g_dist[N_EDGES];

__global__ void geom_kernel(const float* __restrict__ pos,
                            const int* __restrict__ ei) {
    int e = blockIdx.x * blockDim.x + threadIdx.x;
    if (e >= N_EDGES) return;
    int s = ei[e];
    int d = ei[N_EDGES + e];
    float rx = pos[3 * s + 0] - pos[3 * d + 0];
    float ry = pos[3 * s + 1] - pos[3 * d + 1];
    float rz = pos[3 * s + 2] - pos[3 * d + 2];
    float r  = sqrtf(rx * rx + ry * ry + rz * rz);
    float inv = 1.0f / r;
    g_unit[e] = make_float4(rx * inv, ry * inv, rz * inv, 0.0f);
    g_dist[e] = r;
}

__global__ void edge_kernel(const float* __restrict__ h0,
                            const float* __restrict__ h1,
                            const float* __restrict__ h2,
                            const int*   __restrict__ ei,
                            float* __restrict__ out) {
    int idx = blockIdx.x * blockDim.x + threadIdx.x;
    if (idx >= TOTAL) return;
    int e = idx >> 4;
    int k = idx & 15;

    // radial: faithful reshape of [K,E] -> [E,K]:
    // flat = e*16+k ; n_idx = flat / E ; e_idx = flat % E ; uses dists[e_idx]!
    int n_idx = idx / N_EDGES;
    int e_idx = idx - n_idx * N_EDGES;
    float r2  = g_dist[e_idx];
    // sqrt(2/RCUT) * sin(n*pi*r/RCUT) / r
    float rho = 0.44721359549995794f *
                sinf((float)(n_idx + 1) * ((float)M_PI / RCUT) * r2) / r2;

    float4 uu = g_unit[e];
    float ux = uu.x, uy = uu.y, uz = uu.z;

    int src = ei[e];
    int dst = ei[N_EDGES + e];
    int base = dst * NCH + k;

    float s = __ldg(h0 + base);
    const float* vp = h1 + (size_t)base * 3;
    float vx = __ldg(vp + 0), vy = __ldg(vp + 1), vz = __ldg(vp + 2);
    const float* Mp = h2 + (size_t)base * 9;
    float M00 = __ldg(Mp + 0), M01 = __ldg(Mp + 1), M02 = __ldg(Mp + 2);
    float M10 = __ldg(Mp + 3), M11 = __ldg(Mp + 4), M12 = __ldg(Mp + 5);
    float M20 = __ldg(Mp + 6), M21 = __ldg(Mp + 7), M22 = __ldg(Mp + 8);

    float vd = vx * ux + vy * uy + vz * uz;
    float tr = M00 + M11 + M22;
    float Mux = M00 * ux + M01 * uy + M02 * uz;
    float Muy = M10 * ux + M11 * uy + M12 * uz;
    float Muz = M20 * ux + M21 * uy + M22 * uz;
    float Mtux = M00 * ux + M10 * uy + M20 * uz;
    float Mtuy = M01 * ux + M11 * uy + M21 * uz;
    float Mtuz = M02 * ux + M12 * uy + M22 * uz;
    float uMu = ux * Mux + uy * Muy + uz * Muz;

    int ob = src * NCH + k;

    // ---- out0 ----
    atomicAdd(out + ob, rho * (2.0f * s + vd + 2.0f * tr + 2.0f * uMu));

    // ---- out1: rho*( (s + 2*vd + tr)*u + 2*v + (M+Mt)u ) ----
    float c1 = rho * (s + 2.0f * vd + tr);
    float* o1 = out + OUT1_OFF + (size_t)ob * 3;
    atomicAdd(o1 + 0, c1 * ux + rho * (2.0f * vx + Mux + Mtux));
    atomicAdd(o1 + 1, c1 * uy + rho * (2.0f * vy + Muy + Mtuy));
    atomicAdd(o1 + 2, c1 * uz + rho * (2.0f * vz + Muz + Mtuz));

    // ---- out2: rho*2*M_ij + a_i * u_j ----
    // a_i = rho*( (s+tr)*u_i + v_i + 2*(Mu_i + Mtu_i) )
    float ct = rho * (s + tr);
    float ax = ct * ux + rho * (vx + 2.0f * (Mux + Mtux));
    float ay = ct * uy + rho * (vy + 2.0f * (Muy + Mtuy));
    float az = ct * uz + rho * (vz + 2.0f * (Muz + Mtuz));
    float r2m = 2.0f * rho;
    float* o2 = out + OUT2_OFF + (size_t)ob * 9;
    atomicAdd(o2 + 0, r2m * M00 + ax * ux);
    atomicAdd(o2 + 1, r2m * M01 + ax * uy);
    atomicAdd(o2 + 2, r2m * M02 + ax * uz);
    atomicAdd(o2 + 3, r2m * M10 + ay * ux);
    atomicAdd(o2 + 4, r2m * M11 + ay * uy);
    atomicAdd(o2 + 5, r2m * M12 + ay * uz);
    atomicAdd(o2 + 6, r2m * M20 + az * ux);
    atomicAdd(o2 + 7, r2m * M21 + az * uy);
    atomicAdd(o2 + 8, r2m * M22 + az * uz);
}

extern "C" void kernel_launch(void* const* d_in, const int* in_sizes, int n_in,
                              void* d_out, int out_size) {
    const float* h0  = (const float*)d_in[0];
    const float* h1  = (const float*)d_in[1];
    const float* h2  = (const float*)d_in[2];
    const float* pos = (const float*)d_in[3];
    // d_in[4] = channel_weights (unused by the reference output)
    const int*   ei  = (const int*)d_in[5];
    float* out = (float*)d_out;

    cudaMemsetAsync(out, 0, (size_t)out_size * sizeof(float), 0);

    geom_kernel<<<(N_EDGES + 255) / 256, 256>>>(pos, ei);
    edge_kernel<<<(TOTAL + 255) / 256, 256>>>(h0, h1, h2, ei, out);
}

// round 2
// speedup vs baseline: 1.7312x; 1.7312x over previous
#include <cuda_runtime.h>
#include <math.h>

#define N_NODES  50000
#define N_EDGES  400000
#define NCH      16
#define RCUT     10.0f
#define TOTAL_NK (N_NODES * NCH)            // 800000 gather threads
#define OUT1_OFF (N_NODES * NCH)            // 800000
#define OUT2_OFF (N_NODES * NCH * 4)        // 3200000

// ---- scratch (__device__ globals: no allocation allowed) ----
__device__ float4 g_unit[N_EDGES];          // ux,uy,uz,(unused)
__device__ float  g_dist[N_EDGES];
__device__ int    g_cnt[N_NODES];           // degree histogram (by src)
__device__ int    g_off[N_NODES];           // CSR start offsets
__device__ int    g_cur[N_NODES];           // scatter cursors
__device__ int    g_elist[N_EDGES];         // edge ids grouped by src

// ---------------------------------------------------------------------------
__global__ void zero_kernel() {
    int i = blockIdx.x * blockDim.x + threadIdx.x;
    if (i < N_NODES) g_cnt[i] = 0;
}

// geometry + degree histogram
__global__ void geom_kernel(const float* __restrict__ pos,
                            const int* __restrict__ ei) {
    int e = blockIdx.x * blockDim.x + threadIdx.x;
    if (e >= N_EDGES) return;
    int s = ei[e];
    int d = ei[N_EDGES + e];
    float rx = pos[3 * s + 0] - pos[3 * d + 0];
    float ry = pos[3 * s + 1] - pos[3 * d + 1];
    float rz = pos[3 * s + 2] - pos[3 * d + 2];
    float r  = sqrtf(rx * rx + ry * ry + rz * rz);
    float inv = 1.0f / r;
    g_unit[e] = make_float4(rx * inv, ry * inv, rz * inv, 0.0f);
    g_dist[e] = r;
    atomicAdd(&g_cnt[s], 1);
}

// single-block exclusive scan over g_cnt -> g_off, g_cur
__global__ void scan_kernel() {
    __shared__ int sh[1024];
    __shared__ int carry;
    int tid = threadIdx.x;
    if (tid == 0) carry = 0;
    __syncthreads();
    for (int base = 0; base < N_NODES; base += 1024) {
        int i = base + tid;
        int v = (i < N_NODES) ? g_cnt[i] : 0;
        sh[tid] = v;
        __syncthreads();
        #pragma unroll
        for (int d = 1; d < 1024; d <<= 1) {
            int t = (tid >= d) ? sh[tid - d] : 0;
            __syncthreads();
            sh[tid] += t;
            __syncthreads();
        }
        int excl = sh[tid] - v + carry;
        if (i < N_NODES) { g_off[i] = excl; g_cur[i] = excl; }
        __syncthreads();
        if (tid == 0) carry += sh[1023];
        __syncthreads();
    }
}

__global__ void scatter_kernel(const int* __restrict__ ei) {
    int e = blockIdx.x * blockDim.x + threadIdx.x;
    if (e >= N_EDGES) return;
    int s = ei[e];
    int p = atomicAdd(&g_cur[s], 1);
    g_elist[p] = e;
}

// gather-reduce: one thread per (node, channel). Writes every output once.
__global__ void gather_kernel(const float* __restrict__ h0,
                              const float* __restrict__ h1,
                              const float* __restrict__ h2,
                              const int*   __restrict__ ei,
                              float* __restrict__ out) {
    int idx = blockIdx.x * blockDim.x + threadIdx.x;
    if (idx >= TOTAL_NK) return;
    int n = idx >> 4;
    int k = idx & 15;

    int beg = g_off[n];
    int end = beg + g_cnt[n];

    float a0 = 0.0f;
    float a1x = 0.0f, a1y = 0.0f, a1z = 0.0f;
    float a2[9] = {0,0,0,0,0,0,0,0,0};

    for (int p = beg; p < end; ++p) {
        int e = g_elist[p];               // broadcast across the 16 k-lanes

        // radial: faithful [K,E]->[E,K] reshape quirk
        int flat  = e * NCH + k;
        int n_idx = flat / N_EDGES;
        int e_idx = flat - n_idx * N_EDGES;
        float rr  = g_dist[e_idx];
        float rho = 0.44721359549995794f *
                    sinf((float)(n_idx + 1) * ((float)M_PI / RCUT) * rr) / rr;

        float4 uu = g_unit[e];
        float ux = uu.x, uy = uu.y, uz = uu.z;

        int dst  = ei[N_EDGES + e];
        int base = dst * NCH + k;

        float s = __ldg(h0 + base);
        const float* vp = h1 + (size_t)base * 3;
        float vx = __ldg(vp + 0), vy = __ldg(vp + 1), vz = __ldg(vp + 2);
        const float* Mp = h2 + (size_t)base * 9;
        float M00 = __ldg(Mp + 0), M01 = __ldg(Mp + 1), M02 = __ldg(Mp + 2);
        float M10 = __ldg(Mp + 3), M11 = __ldg(Mp + 4), M12 = __ldg(Mp + 5);
        float M20 = __ldg(Mp + 6), M21 = __ldg(Mp + 7), M22 = __ldg(Mp + 8);

        float vd = vx * ux + vy * uy + vz * uz;
        float tr = M00 + M11 + M22;
        float Mux  = M00 * ux + M01 * uy + M02 * uz;
        float Muy  = M10 * ux + M11 * uy + M12 * uz;
        float Muz  = M20 * ux + M21 * uy + M22 * uz;
        float Mtux = M00 * ux + M10 * uy + M20 * uz;
        float Mtuy = M01 * ux + M11 * uy + M21 * uz;
        float Mtuz = M02 * ux + M12 * uy + M22 * uz;
        float uMu  = ux * Mux + uy * Muy + uz * Muz;

        // out0
        a0 += rho * (2.0f * s + vd + 2.0f * tr + 2.0f * uMu);

        // out1 = rho*( (s + 2*vd + tr)*u + 2*v + (M+Mt)u )
        float c1 = rho * (s + 2.0f * vd + tr);
        a1x += c1 * ux + rho * (2.0f * vx + Mux + Mtux);
        a1y += c1 * uy + rho * (2.0f * vy + Muy + Mtuy);
        a1z += c1 * uz + rho * (2.0f * vz + Muz + Mtuz);

        // out2 = 2*rho*M + a (x) u ; a = rho*((s+tr)*u + v + 2*(Mu+Mtu))
        float ct = rho * (s + tr);
        float ax = ct * ux + rho * (vx + 2.0f * (Mux + Mtux));
        float ay = ct * uy + rho * (vy + 2.0f * (Muy + Mtuy));
        float az = ct * uz + rho * (vz + 2.0f * (Muz + Mtuz));
        float r2m = 2.0f * rho;
        a2[0] += r2m * M00 + ax * ux;
        a2[1] += r2m * M01 + ax * uy;
        a2[2] += r2m * M02 + ax * uz;
        a2[3] += r2m * M10 + ay * ux;
        a2[4] += r2m * M11 + ay * uy;
        a2[5] += r2m * M12 + ay * uz;
        a2[6] += r2m * M20 + az * ux;
        a2[7] += r2m * M21 + az * uy;
        a2[8] += r2m * M22 + az * uz;
    }

    out[idx] = a0;
    float* o1 = out + OUT1_OFF + (size_t)idx * 3;
    o1[0] = a1x; o1[1] = a1y; o1[2] = a1z;
    float* o2 = out + OUT2_OFF + (size_t)idx * 9;
    #pragma unroll
    for (int j = 0; j < 9; ++j) o2[j] = a2[j];
}

extern "C" void kernel_launch(void* const* d_in, const int* in_sizes, int n_in,
                              void* d_out, int out_size) {
    const float* h0  = (const float*)d_in[0];
    const float* h1  = (const float*)d_in[1];
    const float* h2  = (const float*)d_in[2];
    const float* pos = (const float*)d_in[3];
    // d_in[4] = channel_weights (provably unused by reference output)
    const int*   ei  = (const int*)d_in[5];
    float* out = (float*)d_out;

    zero_kernel<<<(N_NODES + 255) / 256, 256>>>();
    geom_kernel<<<(N_EDGES + 255) / 256, 256>>>(pos, ei);
    scan_kernel<<<1, 1024>>>();
    scatter_kernel<<<(N_EDGES + 255) / 256, 256>>>(ei);
    gather_kernel<<<(TOTAL_NK + 255) / 256, 256>>>(h0, h1, h2, ei, out);
}

// round 3
// speedup vs baseline: 3.7497x; 2.1659x over previous
#include <cuda_runtime.h>
#include <math.h>

#define N_NODES  50000
#define N_EDGES  400000
#define NCH      16
#define RCUT     10.0f
#define MAX_DEG  128
#define TOTAL_NK (N_NODES * NCH)            // 800000 gather threads
#define OUT1_OFF (N_NODES * NCH)            // 800000
#define OUT2_OFF (N_NODES * NCH * 4)        // 3200000

// ---- scratch (__device__ globals: no allocation allowed) ----
__device__ float4 g_unit[N_EDGES];          // ux,uy,uz,(unused)
__device__ float  g_dist[N_EDGES];
__device__ int    g_cnt[N_NODES];           // degree by src
__device__ int    g_slot[N_NODES * MAX_DEG]; // edge ids bucketed by src

__global__ void zero_kernel() {
    int i = blockIdx.x * blockDim.x + threadIdx.x;
    if (i < N_NODES) g_cnt[i] = 0;
}

// geometry + direct bucket scatter (no scan needed)
__global__ void geom_kernel(const float* __restrict__ pos,
                            const int* __restrict__ ei) {
    int e = blockIdx.x * blockDim.x + threadIdx.x;
    if (e >= N_EDGES) return;
    int s = ei[e];
    int d = ei[N_EDGES + e];
    float rx = pos[3 * s + 0] - pos[3 * d + 0];
    float ry = pos[3 * s + 1] - pos[3 * d + 1];
    float rz = pos[3 * s + 2] - pos[3 * d + 2];
    float r  = sqrtf(rx * rx + ry * ry + rz * rz);
    float inv = 1.0f / r;
    g_unit[e] = make_float4(rx * inv, ry * inv, rz * inv, 0.0f);
    g_dist[e] = r;
    int rank = atomicAdd(&g_cnt[s], 1);
    g_slot[s * MAX_DEG + rank] = e;
}

// gather-reduce: one thread per (node, channel). Writes every output once.
__global__ void __launch_bounds__(256)
gather_kernel(const float* __restrict__ h0,
              const float* __restrict__ h1,
              const float* __restrict__ h2,
              const int*   __restrict__ ei,
              float* __restrict__ out) {
    int idx = blockIdx.x * blockDim.x + threadIdx.x;
    if (idx >= TOTAL_NK) return;
    int n = idx >> 4;
    int k = idx & 15;

    int cnt = g_cnt[n];
    const int* slots = g_slot + n * MAX_DEG;

    float a0 = 0.0f;
    float a1x = 0.0f, a1y = 0.0f, a1z = 0.0f;
    float a2[9] = {0,0,0,0,0,0,0,0,0};

    for (int j = 0; j < cnt; ++j) {
        int e = __ldg(slots + j);         // broadcast across the 16 k-lanes

        // radial: faithful [K,E]->[E,K] reshape quirk
        int flat  = e * NCH + k;
        int n_idx = flat / N_EDGES;
        int e_idx = flat - n_idx * N_EDGES;
        float rr  = g_dist[e_idx];
        float rho = 0.44721359549995794f *
                    __sinf((float)(n_idx + 1) * ((float)M_PI / RCUT) * rr) / rr;

        float4 uu = g_unit[e];
        float ux = uu.x, uy = uu.y, uz = uu.z;

        int dst  = ei[N_EDGES + e];
        int base = dst * NCH + k;

        float s = __ldg(h0 + base);
        const float* vp = h1 + (size_t)base * 3;
        float vx = __ldg(vp + 0), vy = __ldg(vp + 1), vz = __ldg(vp + 2);
        const float* Mp = h2 + (size_t)base * 9;
        float M00 = __ldg(Mp + 0), M01 = __ldg(Mp + 1), M02 = __ldg(Mp + 2);
        float M10 = __ldg(Mp + 3), M11 = __ldg(Mp + 4), M12 = __ldg(Mp + 5);
        float M20 = __ldg(Mp + 6), M21 = __ldg(Mp + 7), M22 = __ldg(Mp + 8);

        float vd = vx * ux + vy * uy + vz * uz;
        float tr = M00 + M11 + M22;
        float Mux  = M00 * ux + M01 * uy + M02 * uz;
        float Muy  = M10 * ux + M11 * uy + M12 * uz;
        float Muz  = M20 * ux + M21 * uy + M22 * uz;
        float Mtux = M00 * ux + M10 * uy + M20 * uz;
        float Mtuy = M01 * ux + M11 * uy + M21 * uz;
        float Mtuz = M02 * ux + M12 * uy + M22 * uz;
        float uMu  = ux * Mux + uy * Muy + uz * Muz;

        // out0
        a0 += rho * (2.0f * s + vd + 2.0f * tr + 2.0f * uMu);

        // out1 = rho*( (s + 2*vd + tr)*u + 2*v + (M+Mt)u )
        float c1 = rho * (s + 2.0f * vd + tr);
        a1x += c1 * ux + rho * (2.0f * vx + Mux + Mtux);
        a1y += c1 * uy + rho * (2.0f * vy + Muy + Mtuy);
        a1z += c1 * uz + rho * (2.0f * vz + Muz + Mtuz);

        // out2 = 2*rho*M + a (x) u ; a = rho*((s+tr)*u + v + 2*(Mu+Mtu))
        float ct = rho * (s + tr);
        float ax = ct * ux + rho * (vx + 2.0f * (Mux + Mtux));
        float ay = ct * uy + rho * (vy + 2.0f * (Muy + Mtuy));
        float az = ct * uz + rho * (vz + 2.0f * (Muz + Mtuz));
        float r2m = 2.0f * rho;
        a2[0] += r2m * M00 + ax * ux;
        a2[1] += r2m * M01 + ax * uy;
        a2[2] += r2m * M02 + ax * uz;
        a2[3] += r2m * M10 + ay * ux;
        a2[4] += r2m * M11 + ay * uy;
        a2[5] += r2m * M12 + ay * uz;
        a2[6] += r2m * M20 + az * ux;
        a2[7] += r2m * M21 + az * uy;
        a2[8] += r2m * M22 + az * uz;
    }

    out[idx] = a0;
    float* o1 = out + OUT1_OFF + (size_t)idx * 3;
    o1[0] = a1x; o1[1] = a1y; o1[2] = a1z;
    float* o2 = out + OUT2_OFF + (size_t)idx * 9;
    #pragma unroll
    for (int j = 0; j < 9; ++j) o2[j] = a2[j];
}

extern "C" void kernel_launch(void* const* d_in, const int* in_sizes, int n_in,
                              void* d_out, int out_size) {
    const float* h0  = (const float*)d_in[0];
    const float* h1  = (const float*)d_in[1];
    const float* h2  = (const float*)d_in[2];
    const float* pos = (const float*)d_in[3];
    // d_in[4] = channel_weights (provably unused by reference output)
    const int*   ei  = (const int*)d_in[5];
    float* out = (float*)d_out;

    zero_kernel<<<(N_NODES + 255) / 256, 256>>>();
    geom_kernel<<<(N_EDGES + 255) / 256, 256>>>(pos, ei);
    gather_kernel<<<(TOTAL_NK + 255) / 256, 256>>>(h0, h1, h2, ei, out);
}

// round 4
// speedup vs baseline: 3.7512x; 1.0004x over previous
#include <cuda_runtime.h>
#include <math.h>

#define N_NODES  50000
#define N_EDGES  400000
#define NCH      16
#define RCUT     10.0f
#define MAX_DEG  128
#define TOTAL_NK (N_NODES * NCH)            // 800000 gather threads
#define OUT1_OFF (N_NODES * NCH)            // 800000
#define OUT2_OFF (N_NODES * NCH * 4)        // 3200000

// ---- scratch (__device__ globals: no allocation allowed) ----
__device__ float  g_dist[N_EDGES];
__device__ int    g_cnt[N_NODES];                 // degree by src (zero-init, reset by gather)
__device__ float4 g_rec4[N_NODES * MAX_DEG];      // (ux,uy,uz, dst-as-bits) bucketed by src
__device__ int    g_rece[N_NODES * MAX_DEG];      // original edge id (for radial quirk)

// geometry + direct bucket scatter of full edge records
__global__ void geom_kernel(const float* __restrict__ pos,
                            const int* __restrict__ ei) {
    int e = blockIdx.x * blockDim.x + threadIdx.x;
    if (e >= N_EDGES) return;
    int s = ei[e];
    int d = ei[N_EDGES + e];
    float rx = pos[3 * s + 0] - pos[3 * d + 0];
    float ry = pos[3 * s + 1] - pos[3 * d + 1];
    float rz = pos[3 * s + 2] - pos[3 * d + 2];
    float r  = sqrtf(rx * rx + ry * ry + rz * rz);
    float inv = 1.0f / r;
    g_dist[e] = r;
    int rank = atomicAdd(&g_cnt[s], 1);
    int slot = s * MAX_DEG + rank;
    g_rec4[slot] = make_float4(rx * inv, ry * inv, rz * inv, __int_as_float(d));
    g_rece[slot] = e;
}

// gather-reduce: one thread per (node, channel). Writes every output once.
__global__ void __launch_bounds__(256)
gather_kernel(const float* __restrict__ h0,
              const float* __restrict__ h1,
              const float* __restrict__ h2,
              float* __restrict__ out) {
    int idx = blockIdx.x * blockDim.x + threadIdx.x;
    if (idx >= TOTAL_NK) return;
    int n = idx >> 4;
    int k = idx & 15;

    int cnt = g_cnt[n];
    int off = n * MAX_DEG;

    float a0 = 0.0f;
    float a1x = 0.0f, a1y = 0.0f, a1z = 0.0f;
    float a2[9] = {0,0,0,0,0,0,0,0,0};

    // software-pipelined record fetch
    float4 rec = make_float4(0.f, 0.f, 0.f, 0.f);
    int e = 0;
    if (cnt > 0) { rec = g_rec4[off]; e = g_rece[off]; }

    for (int j = 0; j < cnt; ++j) {
        float4 nrec = rec;
        int ne = e;
        if (j + 1 < cnt) { nrec = g_rec4[off + j + 1]; ne = g_rece[off + j + 1]; }

        // radial: faithful [K,E]->[E,K] reshape quirk
        int flat  = e * NCH + k;
        int n_idx = flat / N_EDGES;
        int e_idx = flat - n_idx * N_EDGES;
        float rr  = g_dist[e_idx];
        float rho = 0.44721359549995794f *
                    __sinf((float)(n_idx + 1) * ((float)M_PI / RCUT) * rr) / rr;

        float ux = rec.x, uy = rec.y, uz = rec.z;
        int dst  = __float_as_int(rec.w);
        int base = dst * NCH + k;

        float s = __ldg(h0 + base);
        const float* vp = h1 + (size_t)base * 3;
        float vx = __ldg(vp + 0), vy = __ldg(vp + 1), vz = __ldg(vp + 2);
        const float* Mp = h2 + (size_t)base * 9;
        float M00 = __ldg(Mp + 0), M01 = __ldg(Mp + 1), M02 = __ldg(Mp + 2);
        float M10 = __ldg(Mp + 3), M11 = __ldg(Mp + 4), M12 = __ldg(Mp + 5);
        float M20 = __ldg(Mp + 6), M21 = __ldg(Mp + 7), M22 = __ldg(Mp + 8);

        float vd = vx * ux + vy * uy + vz * uz;
        float tr = M00 + M11 + M22;
        float Mux  = M00 * ux + M01 * uy + M02 * uz;
        float Muy  = M10 * ux + M11 * uy + M12 * uz;
        float Muz  = M20 * ux + M21 * uy + M22 * uz;
        float Mtux = M00 * ux + M10 * uy + M20 * uz;
        float Mtuy = M01 * ux + M11 * uy + M21 * uz;
        float Mtuz = M02 * ux + M12 * uy + M22 * uz;
        float uMu  = ux * Mux + uy * Muy + uz * Muz;

        // out0
        a0 += rho * (2.0f * s + vd + 2.0f * tr + 2.0f * uMu);

        // out1 = rho*( (s + 2*vd + tr)*u + 2*v + (M+Mt)u )
        float c1 = rho * (s + 2.0f * vd + tr);
        a1x += c1 * ux + rho * (2.0f * vx + Mux + Mtux);
        a1y += c1 * uy + rho * (2.0f * vy + Muy + Mtuy);
        a1z += c1 * uz + rho * (2.0f * vz + Muz + Mtuz);

        // out2 = 2*rho*M + a (x) u ; a = rho*((s+tr)*u + v + 2*(Mu+Mtu))
        float ct = rho * (s + tr);
        float ax = ct * ux + rho * (vx + 2.0f * (Mux + Mtux));
        float ay = ct * uy + rho * (vy + 2.0f * (Muy + Mtuy));
        float az = ct * uz + rho * (vz + 2.0f * (Muz + Mtuz));
        float r2m = 2.0f * rho;
        a2[0] += r2m * M00 + ax * ux;
        a2[1] += r2m * M01 + ax * uy;
        a2[2] += r2m * M02 + ax * uz;
        a2[3] += r2m * M10 + ay * ux;
        a2[4] += r2m * M11 + ay * uy;
        a2[5] += r2m * M12 + ay * uz;
        a2[6] += r2m * M20 + az * ux;
        a2[7] += r2m * M21 + az * uy;
        a2[8] += r2m * M22 + az * uz;

        rec = nrec;
        e = ne;
    }

    out[idx] = a0;
    float* o1 = out + OUT1_OFF + (size_t)idx * 3;
    o1[0] = a1x; o1[1] = a1y; o1[2] = a1z;
    float* o2 = out + OUT2_OFF + (size_t)idx * 9;
    #pragma unroll
    for (int j = 0; j < 9; ++j) o2[j] = a2[j];

    // reset degree counter for the next launch (warp-converged: all 16 k-lanes
    // of node n sit in the same warp and have already read g_cnt[n])
    if (k == 0) g_cnt[n] = 0;
}

extern "C" void kernel_launch(void* const* d_in, const int* in_sizes, int n_in,
                              void* d_out, int out_size) {
    const float* h0  = (const float*)d_in[0];
    const float* h1  = (const float*)d_in[1];
    const float* h2  = (const float*)d_in[2];
    const float* pos = (const float*)d_in[3];
    // d_in[4] = channel_weights (provably unused by reference output)
    const int*   ei  = (const int*)d_in[5];
    float* out = (float*)d_out;

    geom_kernel<<<(N_EDGES + 255) / 256, 256>>>(pos, ei);
    gather_kernel<<<(TOTAL_NK + 255) / 256, 256>>>(h0, h1, h2, out);
}